// round 7
// baseline (speedup 1.0000x reference)
#include <cuda_runtime.h>

#define NB 8
#define NC 256
#define NP 4096
#define NPQ 4224   // max padded compacted columns: round_up(4096+1, 128)

// Scratch (device globals — no allocation allowed)
__device__ float g_pq[NB * NC * NPQ];  // packed q [b][c][p]  (fg cols + bq + 0-pad)
__device__ float g_pk[NB * NC * NPQ];  // packed k [b][c][p]  (bg cols + bk + 0-pad)
__device__ float g_pv[NB * NPQ * NC];  // packed v [b][p][c]
__device__ float g_go[NB * NC * NPQ];  // attention out (packed cols)
__device__ float g_p [NB * NC * NPQ];  // proj out (packed cols)
__device__ int   g_pr[NB * NP];        // rank within own class (fg or bg)
__device__ int   g_cidx[NB * NP];      // packed col for scatter (fg rank, or nf)
__device__ int   g_cnt[NB * 2];        // nf, nb per batch

typedef unsigned long long ull;

__device__ __forceinline__ ull pack2(float lo, float hi) {
    ull r; asm("mov.b64 %0, {%1, %2};" : "=l"(r) : "f"(lo), "f"(hi)); return r;
}
__device__ __forceinline__ float2 unpack2(ull v) {
    float2 r; asm("mov.b64 {%0, %1}, %2;" : "=f"(r.x), "=f"(r.y) : "l"(v)); return r;
}
__device__ __forceinline__ ull fma2(ull a, ull b, ull c) {
    ull d; asm("fma.rn.f32x2 %0, %1, %2, %3;" : "=l"(d) : "l"(a), "l"(b), "l"(c)); return d;
}
__device__ __forceinline__ ull mul2(ull a, ull b) {
    ull d; asm("mul.rn.f32x2 %0, %1, %2;" : "=l"(d) : "l"(a), "l"(b)); return d;
}
__device__ __forceinline__ void cp16(void* dst, const void* src) {
    unsigned s = (unsigned)__cvta_generic_to_shared(dst);
    asm volatile("cp.async.cg.shared.global [%0], [%1], 16;" :: "r"(s), "l"(src));
}
__device__ __forceinline__ void cp4(void* dst, const void* src) {
    unsigned s = (unsigned)__cvta_generic_to_shared(dst);
    asm volatile("cp.async.ca.shared.global [%0], [%1], 4;" :: "r"(s), "l"(src));
}
#define CP_COMMIT asm volatile("cp.async.commit_group;" ::: "memory")
#define CP_WAIT(n) asm volatile("cp.async.wait_group %0;" :: "n"(n) : "memory")

// ============================================================================
// Compaction: deterministic prefix scan of the 0/1 mask per batch.
// ============================================================================
__global__ __launch_bounds__(256, 1) void compact_kernel(const float* __restrict__ mask)
{
    const int b = blockIdx.x;
    const int tid = threadIdx.x;
    const int lane = tid & 31, wid = tid >> 5;
    __shared__ int wsum[8];
    __shared__ int s_nf;

    bool f[16];
    int c = 0;
    const float* mb = mask + (size_t)b * NP;
    #pragma unroll
    for (int i = 0; i < 16; i++) { f[i] = mb[tid * 16 + i] > 0.5f; c += f[i]; }

    int v = c;
    #pragma unroll
    for (int off = 1; off < 32; off <<= 1) {
        int u = __shfl_up_sync(0xffffffffu, v, off);
        if (lane >= off) v += u;
    }
    if (lane == 31) wsum[wid] = v;
    __syncthreads();
    if (tid < 8) {
        int wv = wsum[tid];
        #pragma unroll
        for (int off = 1; off < 8; off <<= 1) {
            int u = __shfl_up_sync(0xffu, wv, off);
            if (tid >= off) wv += u;
        }
        wsum[tid] = wv;
        if (tid == 7) s_nf = wv;
    }
    __syncthreads();
    const int nf = s_nf;
    int excl = v - c + (wid ? wsum[wid - 1] : 0);
    int fo = excl;
    int bo = tid * 16 - excl;

    int* pr   = g_pr   + (size_t)b * NP;
    int* cidx = g_cidx + (size_t)b * NP;
    #pragma unroll
    for (int i = 0; i < 16; i++) {
        int n = tid * 16 + i;
        if (f[i]) { pr[n] = fo; cidx[n] = fo; fo++; }
        else      { pr[n] = bo; cidx[n] = nf; bo++; }
    }
    if (tid == 0) { g_cnt[b * 2] = nf; g_cnt[b * 2 + 1] = NP - nf; }
}

// ============================================================================
// Kernel A: fused dense QKV projection, cp.async double-buffered, epilogue
// writes DIRECTLY into compacted buffers. 2 CTAs/SM.
// ============================================================================
__global__ __launch_bounds__(256, 2) void qkv_kernel(
    const float* __restrict__ x, const float* __restrict__ mask,
    const float* __restrict__ Wq, const float* __restrict__ bq,
    const float* __restrict__ Wk, const float* __restrict__ bk,
    const float* __restrict__ Wv, const float* __restrict__ bv)
{
    __shared__ float Ws[2][32][132];
    __shared__ float Xs[2][32][64];

    const int tid = threadIdx.x;
    const int tx = tid & 15;
    const int ty = tid >> 4;
    const int n0 = blockIdx.x * 64;
    const int m0 = blockIdx.y * 128;
    const int b  = blockIdx.z;

    ull acc[4][4];
    #pragma unroll
    for (int mp = 0; mp < 4; mp++)
        #pragma unroll
        for (int jj = 0; jj < 4; jj++) acc[mp][jj] = 0ull;

    auto issue = [&](int ci, int buf) {
        const int kc = ci * 32;
        #pragma unroll
        for (int it = 0; it < 16; it++) {
            int idx = tid + it * 256;
            int m = idx >> 5, kk = idx & 31;
            int mg = m0 + m;
            const float* Wp = (mg < 256) ? Wq : ((mg < 512) ? Wk : Wv);
            cp4(&Ws[buf][kk][m], &Wp[(mg & 255) * 256 + kc + kk]);
        }
        #pragma unroll
        for (int it = 0; it < 2; it++) {
            int idx = tid + it * 256;
            int k = idx >> 4, j4 = idx & 15;
            cp16(&Xs[buf][k][j4 * 4], &x[(size_t)(b * NC + kc + k) * NP + n0 + j4 * 4]);
        }
        CP_COMMIT;
    };

    issue(0, 0);
    for (int ci = 0; ci < 8; ci++) {
        int nxt = (ci + 1 < 8) ? ci + 1 : 7;
        issue(nxt, (ci + 1) & 1);
        CP_WAIT(1);
        __syncthreads();
        const int buf = ci & 1;
        #pragma unroll 8
        for (int k = 0; k < 32; k++) {
            ulonglong2 w01 = *reinterpret_cast<const ulonglong2*>(&Ws[buf][k][ty * 8]);
            ulonglong2 w23 = *reinterpret_cast<const ulonglong2*>(&Ws[buf][k][ty * 8 + 4]);
            float4 xv = *reinterpret_cast<const float4*>(&Xs[buf][k][tx * 4]);
            ull wp[4] = { w01.x, w01.y, w23.x, w23.y };
            ull xd[4] = { pack2(xv.x, xv.x), pack2(xv.y, xv.y),
                          pack2(xv.z, xv.z), pack2(xv.w, xv.w) };
            #pragma unroll
            for (int mp = 0; mp < 4; mp++)
                #pragma unroll
                for (int jj = 0; jj < 4; jj++)
                    acc[mp][jj] = fma2(wp[mp], xd[jj], acc[mp][jj]);
        }
        __syncthreads();
    }
    CP_WAIT(0);

    const int sel = m0 >> 8;
    const int nbase = n0 + tx * 4;
    float mk[4]; int pr[4];
    #pragma unroll
    for (int jj = 0; jj < 4; jj++) {
        mk[jj] = mask[(size_t)b * NP + nbase + jj];
        pr[jj] = g_pr[(size_t)b * NP + nbase + jj];
    }

    #pragma unroll
    for (int mp = 0; mp < 4; mp++) {
        float2 u[4];
        #pragma unroll
        for (int jj = 0; jj < 4; jj++) u[jj] = unpack2(acc[mp][jj]);
        #pragma unroll
        for (int h = 0; h < 2; h++) {
            const int o = (m0 & 255) + ty * 8 + mp * 2 + h;
            float val[4];
            val[0] = h ? u[0].y : u[0].x;
            val[1] = h ? u[1].y : u[1].x;
            val[2] = h ? u[2].y : u[2].x;
            val[3] = h ? u[3].y : u[3].x;
            if (sel == 0) {
                const float bb = bq[o];
                float* dst = g_pq + (size_t)(b * NC + o) * NPQ;
                #pragma unroll
                for (int jj = 0; jj < 4; jj++)
                    if (mk[jj] > 0.5f) dst[pr[jj]] = val[jj] + bb;
            } else if (sel == 1) {
                const float bb = bk[o];
                float* dst = g_pk + (size_t)(b * NC + o) * NPQ;
                #pragma unroll
                for (int jj = 0; jj < 4; jj++)
                    if (mk[jj] < 0.5f) dst[pr[jj]] = val[jj] + bb;
            } else {
                const float bb = bv[o];
                #pragma unroll
                for (int jj = 0; jj < 4; jj++)
                    if (mk[jj] < 0.5f)
                        g_pv[((size_t)b * NPQ + pr[jj]) * NC + o] = val[jj] + bb;
            }
        }
    }
}

// ============================================================================
// Pad: shared bias column + zero pad. Queries pad to 64, keys to 128.
// ============================================================================
__global__ __launch_bounds__(256, 1) void pad_kernel(
    const float* __restrict__ bq, const float* __restrict__ bk,
    const float* __restrict__ bv)
{
    const int b = blockIdx.x;
    const int sec = blockIdx.y;
    const int tid = threadIdx.x;
    const int nf = g_cnt[b * 2];
    const int nb = g_cnt[b * 2 + 1];

    if (sec == 0) {
        const int NQ = ((nf + 64) >> 6) << 6;
        const int npad = NQ - nf;
        for (int idx = tid; idx < npad * NC; idx += 256) {
            int c = idx / npad, p = nf + idx % npad;
            g_pq[(size_t)(b * NC + c) * NPQ + p] = (p == nf) ? bq[c] : 0.f;
        }
    } else if (sec == 1) {
        const int NK = ((nb + 128) >> 7) << 7;
        const int npad = NK - nb;
        for (int idx = tid; idx < npad * NC; idx += 256) {
            int c = idx / npad, p = nb + idx % npad;
            g_pk[(size_t)(b * NC + c) * NPQ + p] = (p == nb) ? bk[c] : 0.f;
        }
    } else {
        const int NK = ((nb + 128) >> 7) << 7;
        for (int p = nb; p < NK; p++)
            g_pv[((size_t)b * NPQ + p) * NC + tid] = (p == nb) ? bv[tid] : 0.f;
    }
}

// ============================================================================
// Kernel B: flash attention, 512 threads, tile 64q x 128k, c-chunked.
// Phase schedule (two 64KB buffers A/B ping-pong through phases):
//   A: S0 reads bufA(K c0..127)   | load K c128..255 -> bufB
//   B: S1 reads bufB(K c128..255) | load V c0..127   -> bufA ; softmax -> Ps
//   C: PV0 reads bufA(V c0..127)  | load V c128..255 -> bufB
//   D: PV1 reads bufB(V c128..255)| load next K c0..127 -> bufA
// Per phase: CP_WAIT(0); __syncthreads(); issue next load; compute.
// Thread map: tx=tid&31, ty=tid>>5. S: rows ty*4..+3 (i-pair packed),
// cols tx*4..+3. PV: c = h*128 + tx*4..+3, rows ty*4..+3.
// ============================================================================
__global__ __launch_bounds__(512, 1) void attn_kernel()
{
    extern __shared__ float smf[];
    float* Qs   = smf;              // [256 c][64 i]   = 16384 floats
    float* BufA = smf + 16384;      // 16384 floats (K or V chunk)
    float* BufB = smf + 32768;      // 16384 floats
    float* Ps   = smf + 49152;      // [64 i][128 j]   = 8192 floats

    const int tid = threadIdx.x;
    const int tx = tid & 31;
    const int ty = tid >> 5;
    const int b  = blockIdx.y;
    const int i0 = blockIdx.x * 64;

    const int nf = g_cnt[b * 2];
    const int nb = g_cnt[b * 2 + 1];
    if (i0 >= nf + 1) return;
    const int nkt = (nb + 128) >> 7;    // 128-key tiles (incl. shared bk key)
    const float wF = (float)nf;

    // chunk loads: K chunk h (c in [h*128, h*128+128)) of key tile j0 -> buf[c][j]
    auto loadK = [&](int h, int j0, float* buf) {
        const float* src = g_pk + (size_t)(b * NC + h * 128) * NPQ + j0;
        #pragma unroll
        for (int it = 0; it < 8; it++) {
            int idx = tid + it * 512;
            int c = idx >> 5, j4 = idx & 31;
            cp16(&buf[c * 128 + j4 * 4], &src[(size_t)c * NPQ + j4 * 4]);
        }
        CP_COMMIT;
    };
    // V chunk h of key tile j0 -> buf[j][c]
    auto loadV = [&](int h, int j0, float* buf) {
        const float* src = g_pv + ((size_t)b * NPQ + j0) * NC + h * 128;
        #pragma unroll
        for (int it = 0; it < 8; it++) {
            int idx = tid + it * 512;
            int j = idx >> 5, c4 = idx & 31;
            cp16(&buf[j * 128 + c4 * 4], &src[(size_t)j * NC + c4 * 4]);
        }
        CP_COMMIT;
    };

    // prologue group: Q (resident) + K chunk0 of tile 0 -> BufA
    #pragma unroll
    for (int it = 0; it < 8; it++) {
        int idx = tid + it * 512;
        int c = idx >> 4, i4 = idx & 15;
        cp16(&Qs[c * 64 + i4 * 4], &g_pq[(size_t)(b * NC + c) * NPQ + i0 + i4 * 4]);
    }
    loadK(0, 0, BufA);   // commits Q+K0 together

    float m_i[4], l_i[4];
    #pragma unroll
    for (int ii = 0; ii < 4; ii++) { m_i[ii] = -1e30f; l_i[ii] = 0.f; }
    ulonglong2 oa[2][4];    // [c-chunk][ii], pair over c
    #pragma unroll
    for (int h = 0; h < 2; h++)
        #pragma unroll
        for (int ii = 0; ii < 4; ii++) { oa[h][ii].x = 0ull; oa[h][ii].y = 0ull; }

    for (int jt = 0; jt < nkt; jt++) {
        const int j0 = jt * 128;
        ull s2[2][4];   // [i-pair][jj]
        #pragma unroll
        for (int ip = 0; ip < 2; ip++)
            #pragma unroll
            for (int jj = 0; jj < 4; jj++) s2[ip][jj] = 0ull;

        // ---------------- Phase A: S0 (bufA = K c0) ----------------
        CP_WAIT(0);
        __syncthreads();
        loadK(1, j0, BufB);
        #pragma unroll 4
        for (int c = 0; c < 128; c++) {
            ulonglong2 q2 = *reinterpret_cast<const ulonglong2*>(&Qs[c * 64 + ty * 4]);
            float4 k4 = *reinterpret_cast<const float4*>(&BufA[c * 128 + tx * 4]);
            ull kd[4] = { pack2(k4.x, k4.x), pack2(k4.y, k4.y),
                          pack2(k4.z, k4.z), pack2(k4.w, k4.w) };
            #pragma unroll
            for (int jj = 0; jj < 4; jj++) {
                s2[0][jj] = fma2(q2.x, kd[jj], s2[0][jj]);
                s2[1][jj] = fma2(q2.y, kd[jj], s2[1][jj]);
            }
        }

        // ---------------- Phase B: S1 (bufB = K c1) ----------------
        CP_WAIT(0);
        __syncthreads();
        loadV(0, j0, BufA);
        #pragma unroll 4
        for (int c = 0; c < 128; c++) {
            ulonglong2 q2 = *reinterpret_cast<const ulonglong2*>(&Qs[(128 + c) * 64 + ty * 4]);
            float4 k4 = *reinterpret_cast<const float4*>(&BufB[c * 128 + tx * 4]);
            ull kd[4] = { pack2(k4.x, k4.x), pack2(k4.y, k4.y),
                          pack2(k4.z, k4.z), pack2(k4.w, k4.w) };
            #pragma unroll
            for (int jj = 0; jj < 4; jj++) {
                s2[0][jj] = fma2(q2.x, kd[jj], s2[0][jj]);
                s2[1][jj] = fma2(q2.y, kd[jj], s2[1][jj]);
            }
        }

        // ---- online softmax over this 128-key tile ----
        {
            float sv[4][4];
            #pragma unroll
            for (int ip = 0; ip < 2; ip++)
                #pragma unroll
                for (int jj = 0; jj < 4; jj++) {
                    float2 u = unpack2(s2[ip][jj]);
                    sv[ip * 2 + 0][jj] = u.x;
                    sv[ip * 2 + 1][jj] = u.y;
                }
            const int jbase = j0 + tx * 4;
            float w[4];
            #pragma unroll
            for (int jj = 0; jj < 4; jj++) {
                int jg = jbase + jj;
                w[jj] = (jg == nb) ? wF : 1.f;
                if (jg > nb) {
                    #pragma unroll
                    for (int ii = 0; ii < 4; ii++) sv[ii][jj] = -1e30f;
                }
            }
            #pragma unroll
            for (int ii = 0; ii < 4; ii++) {
                float rm = fmaxf(fmaxf(sv[ii][0], sv[ii][1]), fmaxf(sv[ii][2], sv[ii][3]));
                #pragma unroll
                for (int off = 16; off > 0; off >>= 1)
                    rm = fmaxf(rm, __shfl_xor_sync(0xffffffffu, rm, off));
                float mn = fmaxf(m_i[ii], rm);
                float al = __expf(m_i[ii] - mn);
                float rs = 0.f;
                #pragma unroll
                for (int jj = 0; jj < 4; jj++) {
                    float p = __expf(sv[ii][jj] - mn) * w[jj];
                    sv[ii][jj] = p;
                    rs += p;
                }
                #pragma unroll
                for (int off = 16; off > 0; off >>= 1)
                    rs += __shfl_xor_sync(0xffffffffu, rs, off);
                l_i[ii] = l_i[ii] * al + rs;
                m_i[ii] = mn;
                *reinterpret_cast<float4*>(&Ps[(ty * 4 + ii) * 128 + tx * 4]) =
                    make_float4(sv[ii][0], sv[ii][1], sv[ii][2], sv[ii][3]);
                ull ad = pack2(al, al);
                #pragma unroll
                for (int h = 0; h < 2; h++) {
                    oa[h][ii].x = mul2(oa[h][ii].x, ad);
                    oa[h][ii].y = mul2(oa[h][ii].y, ad);
                }
            }
        }

        // ---------------- Phase C: PV0 (bufA = V c0) ----------------
        CP_WAIT(0);
        __syncthreads();    // also publishes Ps
        loadV(1, j0, BufB);
        for (int j4 = 0; j4 < 32; j4++) {
            float4 pr[4];
            #pragma unroll
            for (int ii = 0; ii < 4; ii++)
                pr[ii] = *reinterpret_cast<const float4*>(&Ps[(ty * 4 + ii) * 128 + j4 * 4]);
            #pragma unroll
            for (int dj = 0; dj < 4; dj++) {
                ulonglong2 vv = *reinterpret_cast<const ulonglong2*>(&BufA[(j4 * 4 + dj) * 128 + tx * 4]);
                #pragma unroll
                for (int ii = 0; ii < 4; ii++) {
                    float p = (dj == 0) ? pr[ii].x : (dj == 1) ? pr[ii].y
                            : (dj == 2) ? pr[ii].z : pr[ii].w;
                    ull pd = pack2(p, p);
                    oa[0][ii].x = fma2(vv.x, pd, oa[0][ii].x);
                    oa[0][ii].y = fma2(vv.y, pd, oa[0][ii].y);
                }
            }
        }

        // ---------------- Phase D: PV1 (bufB = V c1) ----------------
        CP_WAIT(0);
        __syncthreads();
        {
            const int jn = ((jt + 1 < nkt) ? jt + 1 : nkt - 1) * 128;
            loadK(0, jn, BufA);
        }
        for (int j4 = 0; j4 < 32; j4++) {
            float4 pr[4];
            #pragma unroll
            for (int ii = 0; ii < 4; ii++)
                pr[ii] = *reinterpret_cast<const float4*>(&Ps[(ty * 4 + ii) * 128 + j4 * 4]);
            #pragma unroll
            for (int dj = 0; dj < 4; dj++) {
                ulonglong2 vv = *reinterpret_cast<const ulonglong2*>(&BufB[(j4 * 4 + dj) * 128 + tx * 4]);
                #pragma unroll
                for (int ii = 0; ii < 4; ii++) {
                    float p = (dj == 0) ? pr[ii].x : (dj == 1) ? pr[ii].y
                            : (dj == 2) ? pr[ii].z : pr[ii].w;
                    ull pd = pack2(p, p);
                    oa[1][ii].x = fma2(vv.x, pd, oa[1][ii].x);
                    oa[1][ii].y = fma2(vv.y, pd, oa[1][ii].y);
                }
            }
        }
    }
    CP_WAIT(0);

    float inv[4];
    #pragma unroll
    for (int ii = 0; ii < 4; ii++) inv[ii] = 1.f / l_i[ii];

    #pragma unroll
    for (int h = 0; h < 2; h++) {
        float of[4][4];
        #pragma unroll
        for (int ii = 0; ii < 4; ii++) {
            float2 u0 = unpack2(oa[h][ii].x);
            float2 u1 = unpack2(oa[h][ii].y);
            of[ii][0] = u0.x * inv[ii];
            of[ii][1] = u0.y * inv[ii];
            of[ii][2] = u1.x * inv[ii];
            of[ii][3] = u1.y * inv[ii];
        }
        #pragma unroll
        for (int d = 0; d < 4; d++) {
            int c = h * 128 + tx * 4 + d;
            *reinterpret_cast<float4*>(&g_go[(size_t)(b * NC + c) * NPQ + i0 + ty * 4]) =
                make_float4(of[0][d], of[1][d], of[2][d], of[3][d]);
        }
    }
}

// ============================================================================
// Kernel C: output projection on packed columns: g_p = Wo@go + bo
// ============================================================================
__global__ __launch_bounds__(256, 2) void proj_kernel(
    const float* __restrict__ Wo, const float* __restrict__ bo)
{
    __shared__ float Ws[32][132];
    __shared__ float Xs[32][64];

    const int tid = threadIdx.x;
    const int tx = tid & 15;
    const int ty = tid >> 4;
    const int n0 = blockIdx.x * 64;
    const int m0 = blockIdx.y * 128;
    const int b  = blockIdx.z;

    const int nfq = g_cnt[b * 2] + 1;
    if (n0 >= nfq) return;

    ull acc[4][4];
    #pragma unroll
    for (int mp = 0; mp < 4; mp++)
        #pragma unroll
        for (int jj = 0; jj < 4; jj++) acc[mp][jj] = 0ull;

    for (int kc = 0; kc < NC; kc += 32) {
        #pragma unroll
        for (int it = 0; it < 16; it++) {
            int idx = tid + it * 256;
            int m = idx >> 5, kk = idx & 31;
            Ws[kk][m] = Wo[(m0 + m) * 256 + kc + kk];
        }
        #pragma unroll
        for (int it = 0; it < 2; it++) {
            int idx = tid + it * 256;
            int k = idx >> 4, j4 = idx & 15;
            *reinterpret_cast<float4*>(&Xs[k][j4 * 4]) =
                *reinterpret_cast<const float4*>(&g_go[(size_t)(b * NC + kc + k) * NPQ + n0 + j4 * 4]);
        }
        __syncthreads();
        #pragma unroll 8
        for (int k = 0; k < 32; k++) {
            ulonglong2 w01 = *reinterpret_cast<const ulonglong2*>(&Ws[k][ty * 8]);
            ulonglong2 w23 = *reinterpret_cast<const ulonglong2*>(&Ws[k][ty * 8 + 4]);
            float4 xv = *reinterpret_cast<const float4*>(&Xs[k][tx * 4]);
            ull wp[4] = { w01.x, w01.y, w23.x, w23.y };
            ull xd[4] = { pack2(xv.x, xv.x), pack2(xv.y, xv.y),
                          pack2(xv.z, xv.z), pack2(xv.w, xv.w) };
            #pragma unroll
            for (int mp = 0; mp < 4; mp++)
                #pragma unroll
                for (int jj = 0; jj < 4; jj++)
                    acc[mp][jj] = fma2(wp[mp], xd[jj], acc[mp][jj]);
        }
        __syncthreads();
    }

    #pragma unroll
    for (int mp = 0; mp < 4; mp++) {
        float2 u[4];
        #pragma unroll
        for (int jj = 0; jj < 4; jj++) u[jj] = unpack2(acc[mp][jj]);
        #pragma unroll
        for (int h = 0; h < 2; h++) {
            int o = m0 + ty * 8 + mp * 2 + h;
            float bb = bo[o];
            float4 r;
            r.x = (h ? u[0].y : u[0].x) + bb;
            r.y = (h ? u[1].y : u[1].x) + bb;
            r.z = (h ? u[2].y : u[2].x) + bb;
            r.w = (h ? u[3].y : u[3].x) + bb;
            *reinterpret_cast<float4*>(&g_p[(size_t)(b * NC + o) * NPQ + n0 + tx * 4]) = r;
        }
    }
}

// ============================================================================
// Scatter: out[b][c][n] = g_p[b][c][cidx[n]] + gamma * x[b][c][n]
// ============================================================================
__global__ __launch_bounds__(256, 1) void scatter_kernel(
    const float* __restrict__ x, const float* __restrict__ gamma,
    float* __restrict__ out)
{
    const int b = blockIdx.y;
    const int n = blockIdx.x * 256 + threadIdx.x;
    const int ci = g_cidx[(size_t)b * NP + n];
    const float g0 = gamma[0];

    const float* px = x + (size_t)b * NC * NP + n;
    const float* pp = g_p + (size_t)b * NC * NPQ + ci;
    float* po = out + (size_t)b * NC * NP + n;

    #pragma unroll 4
    for (int c = 0; c < NC; c++) {
        po[(size_t)c * NP] = pp[(size_t)c * NPQ] + g0 * px[(size_t)c * NP];
    }
}

extern "C" void kernel_launch(void* const* d_in, const int* in_sizes, int n_in,
                              void* d_out, int out_size)
{
    const float* x     = (const float*)d_in[0];
    const float* mask  = (const float*)d_in[1];
    const float* Wq    = (const float*)d_in[2];
    const float* bq    = (const float*)d_in[3];
    const float* Wk    = (const float*)d_in[4];
    const float* bk    = (const float*)d_in[5];
    const float* Wv    = (const float*)d_in[6];
    const float* bv    = (const float*)d_in[7];
    const float* Wo    = (const float*)d_in[8];
    const float* bo    = (const float*)d_in[9];
    const float* gamma = (const float*)d_in[10];
    float* out = (float*)d_out;

    compact_kernel<<<NB, 256>>>(mask);
    qkv_kernel<<<dim3(64, 6, NB), 256>>>(x, mask, Wq, bq, Wk, bk, Wv, bv);
    pad_kernel<<<dim3(NB, 3), 256>>>(bq, bk, bv);

    const size_t smemB = (size_t)(16384 * 3 + 8192) * sizeof(float);  // 229376 B
    cudaFuncSetAttribute(attn_kernel, cudaFuncAttributeMaxDynamicSharedMemorySize, (int)smemB);
    attn_kernel<<<dim3(65, NB), 512, smemB>>>();

    proj_kernel<<<dim3(65, 2, NB), 256>>>(Wo, bo);
    scatter_kernel<<<dim3(16, NB), 256>>>(x, gamma, out);
}

// round 8
// speedup vs baseline: 1.0391x; 1.0391x over previous
#include <cuda_runtime.h>

#define NB 8
#define NC 256
#define NP 4096
#define NPQ 4224

__device__ float g_pq[NB * NC * NPQ];
__device__ float g_pk[NB * NC * NPQ];
__device__ float g_pv[NB * NPQ * NC];
__device__ float g_go[NB * NC * NPQ];
__device__ float g_p [NB * NC * NPQ];
__device__ int   g_pr[NB * NP];
__device__ int   g_cidx[NB * NP];
__device__ int   g_cnt[NB * 2];

typedef unsigned long long ull;

__device__ __forceinline__ ull pack2(float lo, float hi) {
    ull r; asm("mov.b64 %0, {%1, %2};" : "=l"(r) : "f"(lo), "f"(hi)); return r;
}
__device__ __forceinline__ float2 unpack2(ull v) {
    float2 r; asm("mov.b64 {%0, %1}, %2;" : "=f"(r.x), "=f"(r.y) : "l"(v)); return r;
}
__device__ __forceinline__ ull fma2(ull a, ull b, ull c) {
    ull d; asm("fma.rn.f32x2 %0, %1, %2, %3;" : "=l"(d) : "l"(a), "l"(b), "l"(c)); return d;
}
__device__ __forceinline__ ull mul2(ull a, ull b) {
    ull d; asm("mul.rn.f32x2 %0, %1, %2;" : "=l"(d) : "l"(a), "l"(b)); return d;
}
__device__ __forceinline__ void cp16(void* dst, const void* src) {
    unsigned s = (unsigned)__cvta_generic_to_shared(dst);
    asm volatile("cp.async.cg.shared.global [%0], [%1], 16;" :: "r"(s), "l"(src));
}
__device__ __forceinline__ void cp4(void* dst, const void* src) {
    unsigned s = (unsigned)__cvta_generic_to_shared(dst);
    asm volatile("cp.async.ca.shared.global [%0], [%1], 4;" :: "r"(s), "l"(src));
}
#define CP_COMMIT asm volatile("cp.async.commit_group;" ::: "memory")
#define CP_WAIT(n) asm volatile("cp.async.wait_group %0;" :: "n"(n) : "memory")

// ============================ compaction ===================================
__global__ __launch_bounds__(256, 1) void compact_kernel(const float* __restrict__ mask)
{
    const int b = blockIdx.x;
    const int tid = threadIdx.x;
    const int lane = tid & 31, wid = tid >> 5;
    __shared__ int wsum[8];
    __shared__ int s_nf;

    bool f[16];
    int c = 0;
    const float* mb = mask + (size_t)b * NP;
    #pragma unroll
    for (int i = 0; i < 16; i++) { f[i] = mb[tid * 16 + i] > 0.5f; c += f[i]; }

    int v = c;
    #pragma unroll
    for (int off = 1; off < 32; off <<= 1) {
        int u = __shfl_up_sync(0xffffffffu, v, off);
        if (lane >= off) v += u;
    }
    if (lane == 31) wsum[wid] = v;
    __syncthreads();
    if (tid < 8) {
        int wv = wsum[tid];
        #pragma unroll
        for (int off = 1; off < 8; off <<= 1) {
            int u = __shfl_up_sync(0xffu, wv, off);
            if (tid >= off) wv += u;
        }
        wsum[tid] = wv;
        if (tid == 7) s_nf = wv;
    }
    __syncthreads();
    const int nf = s_nf;
    int excl = v - c + (wid ? wsum[wid - 1] : 0);
    int fo = excl;
    int bo = tid * 16 - excl;

    int* pr   = g_pr   + (size_t)b * NP;
    int* cidx = g_cidx + (size_t)b * NP;
    #pragma unroll
    for (int i = 0; i < 16; i++) {
        int n = tid * 16 + i;
        if (f[i]) { pr[n] = fo; cidx[n] = fo; fo++; }
        else      { pr[n] = bo; cidx[n] = nf; bo++; }
    }
    if (tid == 0) { g_cnt[b * 2] = nf; g_cnt[b * 2 + 1] = NP - nf; }
}

// ============================ QKV projection ===============================
__global__ __launch_bounds__(256, 2) void qkv_kernel(
    const float* __restrict__ x, const float* __restrict__ mask,
    const float* __restrict__ Wq, const float* __restrict__ bq,
    const float* __restrict__ Wk, const float* __restrict__ bk,
    const float* __restrict__ Wv, const float* __restrict__ bv)
{
    __shared__ float Ws[2][32][132];
    __shared__ float Xs[2][32][64];

    const int tid = threadIdx.x;
    const int tx = tid & 15;
    const int ty = tid >> 4;
    const int n0 = blockIdx.x * 64;
    const int m0 = blockIdx.y * 128;
    const int b  = blockIdx.z;

    ull acc[4][4];
    #pragma unroll
    for (int mp = 0; mp < 4; mp++)
        #pragma unroll
        for (int jj = 0; jj < 4; jj++) acc[mp][jj] = 0ull;

    auto issue = [&](int ci, int buf) {
        const int kc = ci * 32;
        #pragma unroll
        for (int it = 0; it < 16; it++) {
            int idx = tid + it * 256;
            int m = idx >> 5, kk = idx & 31;
            int mg = m0 + m;
            const float* Wp = (mg < 256) ? Wq : ((mg < 512) ? Wk : Wv);
            cp4(&Ws[buf][kk][m], &Wp[(mg & 255) * 256 + kc + kk]);
        }
        #pragma unroll
        for (int it = 0; it < 2; it++) {
            int idx = tid + it * 256;
            int k = idx >> 4, j4 = idx & 15;
            cp16(&Xs[buf][k][j4 * 4], &x[(size_t)(b * NC + kc + k) * NP + n0 + j4 * 4]);
        }
        CP_COMMIT;
    };

    issue(0, 0);
    for (int ci = 0; ci < 8; ci++) {
        int nxt = (ci + 1 < 8) ? ci + 1 : 7;
        issue(nxt, (ci + 1) & 1);
        CP_WAIT(1);
        __syncthreads();
        const int buf = ci & 1;
        #pragma unroll 8
        for (int k = 0; k < 32; k++) {
            ulonglong2 w01 = *reinterpret_cast<const ulonglong2*>(&Ws[buf][k][ty * 8]);
            ulonglong2 w23 = *reinterpret_cast<const ulonglong2*>(&Ws[buf][k][ty * 8 + 4]);
            float4 xv = *reinterpret_cast<const float4*>(&Xs[buf][k][tx * 4]);
            ull wp[4] = { w01.x, w01.y, w23.x, w23.y };
            ull xd[4] = { pack2(xv.x, xv.x), pack2(xv.y, xv.y),
                          pack2(xv.z, xv.z), pack2(xv.w, xv.w) };
            #pragma unroll
            for (int mp = 0; mp < 4; mp++)
                #pragma unroll
                for (int jj = 0; jj < 4; jj++)
                    acc[mp][jj] = fma2(wp[mp], xd[jj], acc[mp][jj]);
        }
        __syncthreads();
    }
    CP_WAIT(0);

    const int sel = m0 >> 8;
    const int nbase = n0 + tx * 4;
    float mk[4]; int pr[4];
    #pragma unroll
    for (int jj = 0; jj < 4; jj++) {
        mk[jj] = mask[(size_t)b * NP + nbase + jj];
        pr[jj] = g_pr[(size_t)b * NP + nbase + jj];
    }

    #pragma unroll
    for (int mp = 0; mp < 4; mp++) {
        float2 u[4];
        #pragma unroll
        for (int jj = 0; jj < 4; jj++) u[jj] = unpack2(acc[mp][jj]);
        #pragma unroll
        for (int h = 0; h < 2; h++) {
            const int o = (m0 & 255) + ty * 8 + mp * 2 + h;
            float val[4];
            val[0] = h ? u[0].y : u[0].x;
            val[1] = h ? u[1].y : u[1].x;
            val[2] = h ? u[2].y : u[2].x;
            val[3] = h ? u[3].y : u[3].x;
            if (sel == 0) {
                const float bb = bq[o];
                float* dst = g_pq + (size_t)(b * NC + o) * NPQ;
                #pragma unroll
                for (int jj = 0; jj < 4; jj++)
                    if (mk[jj] > 0.5f) dst[pr[jj]] = val[jj] + bb;
            } else if (sel == 1) {
                const float bb = bk[o];
                float* dst = g_pk + (size_t)(b * NC + o) * NPQ;
                #pragma unroll
                for (int jj = 0; jj < 4; jj++)
                    if (mk[jj] < 0.5f) dst[pr[jj]] = val[jj] + bb;
            } else {
                const float bb = bv[o];
                #pragma unroll
                for (int jj = 0; jj < 4; jj++)
                    if (mk[jj] < 0.5f)
                        g_pv[((size_t)b * NPQ + pr[jj]) * NC + o] = val[jj] + bb;
            }
        }
    }
}

// ============================ pad ==========================================
__global__ __launch_bounds__(256, 1) void pad_kernel(
    const float* __restrict__ bq, const float* __restrict__ bk,
    const float* __restrict__ bv)
{
    const int b = blockIdx.x;
    const int sec = blockIdx.y;
    const int tid = threadIdx.x;
    const int nf = g_cnt[b * 2];
    const int nb = g_cnt[b * 2 + 1];

    if (sec == 0) {
        const int NQ = ((nf + 64) >> 6) << 6;
        const int npad = NQ - nf;
        for (int idx = tid; idx < npad * NC; idx += 256) {
            int c = idx / npad, p = nf + idx % npad;
            g_pq[(size_t)(b * NC + c) * NPQ + p] = (p == nf) ? bq[c] : 0.f;
        }
    } else if (sec == 1) {
        const int NK = ((nb + 128) >> 7) << 7;
        const int npad = NK - nb;
        for (int idx = tid; idx < npad * NC; idx += 256) {
            int c = idx / npad, p = nb + idx % npad;
            g_pk[(size_t)(b * NC + c) * NPQ + p] = (p == nb) ? bk[c] : 0.f;
        }
    } else {
        const int NK = ((nb + 128) >> 7) << 7;
        for (int p = nb; p < NK; p++)
            g_pv[((size_t)b * NPQ + p) * NC + tid] = (p == nb) ? bv[tid] : 0.f;
    }
}

// ============================ flash attention ==============================
// 512 thr, tile 64q x 128k. S: jl=tid&15 -> j quad (jhalf*16+jl)*4,
// rowg=(tid>>4)&15 -> rows rowg*4..+3, jhalf=tid>>8. K in four 64c x 128j
// chunks (32KB). PV: c0=jl*4+jhalf*64, quads {c0, c0+128}; V in two
// 64j x 256c halves (64KB). Pool 4x32KB: K ping-pongs in two while V
// streams through the other two.
__global__ __launch_bounds__(512, 1) void attn_kernel()
{
    extern __shared__ float smf[];
    float* Qs   = smf;              // [256c][64i] 16384
    float* Pool = smf + 16384;      // 4 x 8192
    float* Ps   = smf + 49152;      // [64i][128j] 8192
    float* Red  = smf + 57344;      // 256

    const int tid   = threadIdx.x;
    const int jl    = tid & 15;
    const int rowg  = (tid >> 4) & 15;
    const int jhalf = tid >> 8;
    const int b  = blockIdx.y;
    const int i0 = blockIdx.x * 64;

    const int nf = g_cnt[b * 2];
    const int nb = g_cnt[b * 2 + 1];
    if (i0 >= nf + 1) return;
    const int nkt = (nb + 128) >> 7;
    const float wF = (float)nf;
    const int c0 = jl * 4 + jhalf * 64;

    auto PB = [&](int i) { return Pool + i * 8192; };

    auto loadK = [&](int ck, int j0, float* buf) {
        const float* src = g_pk + (size_t)(b * NC + ck * 64) * NPQ + j0;
        #pragma unroll
        for (int it = 0; it < 4; it++) {
            int idx = tid + it * 512;
            int c = idx >> 5, j4 = idx & 31;
            cp16(&buf[c * 128 + j4 * 4], &src[(size_t)c * NPQ + j4 * 4]);
        }
        CP_COMMIT;
    };
    auto loadV = [&](int vh, int j0, float* buf) {
        const float* src = g_pv + ((size_t)b * NPQ + j0 + vh * 64) * NC;
        #pragma unroll
        for (int it = 0; it < 8; it++) {
            int idx = tid + it * 512;
            int j = idx >> 6, c4 = idx & 63;
            cp16(&buf[j * 256 + c4 * 4], &src[(size_t)j * NC + c4 * 4]);
        }
        CP_COMMIT;
    };

    // prologue: Q + K chunk0 of tile 0 in one group
    #pragma unroll
    for (int it = 0; it < 8; it++) {
        int idx = tid + it * 512;
        int c = idx >> 4, i4 = idx & 15;
        cp16(&Qs[c * 64 + i4 * 4], &g_pq[(size_t)(b * NC + c) * NPQ + i0 + i4 * 4]);
    }
    loadK(0, 0, PB(0));

    float m_i[4], l_i[4];
    #pragma unroll
    for (int ii = 0; ii < 4; ii++) { m_i[ii] = -1e30f; l_i[ii] = 0.f; }
    ulonglong2 oa[2][4];
    #pragma unroll
    for (int q = 0; q < 2; q++)
        #pragma unroll
        for (int ii = 0; ii < 4; ii++) { oa[q][ii].x = 0ull; oa[q][ii].y = 0ull; }

    ull s2[2][4];

    auto sphase = [&](int p, const float* Kb) {
        const float* qb = Qs + (p * 64) * 64 + rowg * 4;
        const float* kb = Kb + (jhalf * 16 + jl) * 4;
        #pragma unroll 8
        for (int c = 0; c < 64; c++) {
            ulonglong2 q2 = *reinterpret_cast<const ulonglong2*>(qb + c * 64);
            float4 k4 = *reinterpret_cast<const float4*>(kb + c * 128);
            ull kd0 = pack2(k4.x, k4.x), kd1 = pack2(k4.y, k4.y);
            ull kd2 = pack2(k4.z, k4.z), kd3 = pack2(k4.w, k4.w);
            s2[0][0] = fma2(q2.x, kd0, s2[0][0]); s2[1][0] = fma2(q2.y, kd0, s2[1][0]);
            s2[0][1] = fma2(q2.x, kd1, s2[0][1]); s2[1][1] = fma2(q2.y, kd1, s2[1][1]);
            s2[0][2] = fma2(q2.x, kd2, s2[0][2]); s2[1][2] = fma2(q2.y, kd2, s2[1][2]);
            s2[0][3] = fma2(q2.x, kd3, s2[0][3]); s2[1][3] = fma2(q2.y, kd3, s2[1][3]);
        }
    };

    auto pvphase = [&](int jb, const float* Vb) {
        #pragma unroll 2
        for (int j4 = 0; j4 < 16; j4++) {
            float4 pr[4];
            #pragma unroll
            for (int ii = 0; ii < 4; ii++)
                pr[ii] = *reinterpret_cast<const float4*>(&Ps[(rowg * 4 + ii) * 128 + jb + j4 * 4]);
            #pragma unroll
            for (int dj = 0; dj < 4; dj++) {
                const float* vrow = Vb + (j4 * 4 + dj) * 256;
                ulonglong2 v0 = *reinterpret_cast<const ulonglong2*>(vrow + c0);
                ulonglong2 v1 = *reinterpret_cast<const ulonglong2*>(vrow + c0 + 128);
                #pragma unroll
                for (int ii = 0; ii < 4; ii++) {
                    float p = (dj == 0) ? pr[ii].x : (dj == 1) ? pr[ii].y
                            : (dj == 2) ? pr[ii].z : pr[ii].w;
                    ull pd = pack2(p, p);
                    oa[0][ii].x = fma2(v0.x, pd, oa[0][ii].x);
                    oa[0][ii].y = fma2(v0.y, pd, oa[0][ii].y);
                    oa[1][ii].x = fma2(v1.x, pd, oa[1][ii].x);
                    oa[1][ii].y = fma2(v1.y, pd, oa[1][ii].y);
                }
            }
        }
    };

    for (int jt = 0; jt < nkt; jt++) {
        const int j0 = jt << 7;
        const int kb = (jt & 1) ? 2 : 0;
        const int vb = 2 - kb;

        #pragma unroll
        for (int ip = 0; ip < 2; ip++)
            #pragma unroll
            for (int jj = 0; jj < 4; jj++) s2[ip][jj] = 0ull;

        CP_WAIT(0); __syncthreads();
        loadK(1, j0, PB(kb ^ 1));
        sphase(0, PB(kb));

        CP_WAIT(0); __syncthreads();
        loadK(2, j0, PB(kb));
        sphase(1, PB(kb ^ 1));

        CP_WAIT(0); __syncthreads();
        loadK(3, j0, PB(kb ^ 1));          // group A
        loadV(0, j0, PB(vb));              // group B -> PB(vb),PB(vb+1)
        sphase(2, PB(kb));

        CP_WAIT(1); __syncthreads();       // K3 done, V0 in flight
        sphase(3, PB(kb ^ 1));

        // ---- softmax over the 128-key tile ----
        {
            float sv[4][4];
            #pragma unroll
            for (int ip = 0; ip < 2; ip++)
                #pragma unroll
                for (int jj = 0; jj < 4; jj++) {
                    float2 u = unpack2(s2[ip][jj]);
                    sv[ip * 2 + 0][jj] = u.x;
                    sv[ip * 2 + 1][jj] = u.y;
                }
            const int jb2 = j0 + (jhalf * 16 + jl) * 4;
            float w[4];
            #pragma unroll
            for (int jj = 0; jj < 4; jj++) {
                int jg = jb2 + jj;
                w[jj] = (jg == nb) ? wF : 1.f;
                if (jg > nb) {
                    #pragma unroll
                    for (int ii = 0; ii < 4; ii++) sv[ii][jj] = -1e30f;
                }
            }
            float mloc[4];
            #pragma unroll
            for (int ii = 0; ii < 4; ii++) {
                float rm = fmaxf(fmaxf(sv[ii][0], sv[ii][1]), fmaxf(sv[ii][2], sv[ii][3]));
                #pragma unroll
                for (int off = 1; off < 16; off <<= 1)
                    rm = fmaxf(rm, __shfl_xor_sync(0xffffffffu, rm, off));
                mloc[ii] = rm;
            }
            if (jl == 0) {
                #pragma unroll
                for (int ii = 0; ii < 4; ii++)
                    Red[jhalf * 64 + rowg * 4 + ii] = mloc[ii];
            }
            __syncthreads();
            float alpha[4], rsum[4];
            #pragma unroll
            for (int ii = 0; ii < 4; ii++) {
                int row = rowg * 4 + ii;
                float mt = fmaxf(Red[row], Red[64 + row]);
                float mn = fmaxf(m_i[ii], mt);
                alpha[ii] = __expf(m_i[ii] - mn);
                m_i[ii] = mn;
                float p0 = __expf(sv[ii][0] - mn) * w[0];
                float p1 = __expf(sv[ii][1] - mn) * w[1];
                float p2 = __expf(sv[ii][2] - mn) * w[2];
                float p3 = __expf(sv[ii][3] - mn) * w[3];
                *reinterpret_cast<float4*>(&Ps[row * 128 + jhalf * 64 + jl * 4]) =
                    make_float4(p0, p1, p2, p3);
                float s = p0 + p1 + p2 + p3;
                #pragma unroll
                for (int off = 1; off < 16; off <<= 1)
                    s += __shfl_xor_sync(0xffffffffu, s, off);
                rsum[ii] = s;
            }
            if (jl == 0) {
                #pragma unroll
                for (int ii = 0; ii < 4; ii++)
                    Red[128 + jhalf * 64 + rowg * 4 + ii] = rsum[ii];
            }
            __syncthreads();
            #pragma unroll
            for (int ii = 0; ii < 4; ii++) {
                int row = rowg * 4 + ii;
                l_i[ii] = l_i[ii] * alpha[ii] + Red[128 + row] + Red[192 + row];
                ull ad = pack2(alpha[ii], alpha[ii]);
                oa[0][ii].x = mul2(oa[0][ii].x, ad);
                oa[0][ii].y = mul2(oa[0][ii].y, ad);
                oa[1][ii].x = mul2(oa[1][ii].x, ad);
                oa[1][ii].y = mul2(oa[1][ii].y, ad);
            }
        }

        CP_WAIT(0); __syncthreads();       // V0 ready; Ps visible
        loadV(1, j0, PB(kb));              // V1 -> PB(kb),PB(kb+1)
        pvphase(0, PB(vb));

        CP_WAIT(0); __syncthreads();
        {
            const int jn = (jt + 1 < nkt) ? (jt + 1) << 7 : j0;
            loadK(0, jn, PB(vb));          // next tile's K base == PB(vb)
        }
        pvphase(64, PB(kb));
    }
    CP_WAIT(0);

    float inv[4];
    #pragma unroll
    for (int ii = 0; ii < 4; ii++) inv[ii] = 1.f / l_i[ii];

    #pragma unroll
    for (int q = 0; q < 2; q++) {
        float of[4][4];
        #pragma unroll
        for (int ii = 0; ii < 4; ii++) {
            float2 u0 = unpack2(oa[q][ii].x);
            float2 u1 = unpack2(oa[q][ii].y);
            of[ii][0] = u0.x * inv[ii];
            of[ii][1] = u0.y * inv[ii];
            of[ii][2] = u1.x * inv[ii];
            of[ii][3] = u1.y * inv[ii];
        }
        #pragma unroll
        for (int d = 0; d < 4; d++) {
            int c = c0 + q * 128 + d;
            *reinterpret_cast<float4*>(&g_go[(size_t)(b * NC + c) * NPQ + i0 + rowg * 4]) =
                make_float4(of[0][d], of[1][d], of[2][d], of[3][d]);
        }
    }
}

// ============================ output projection ============================
__global__ __launch_bounds__(256, 2) void proj_kernel(
    const float* __restrict__ Wo, const float* __restrict__ bo)
{
    __shared__ float Ws[32][132];
    __shared__ float Xs[32][64];

    const int tid = threadIdx.x;
    const int tx = tid & 15;
    const int ty = tid >> 4;
    const int n0 = blockIdx.x * 64;
    const int m0 = blockIdx.y * 128;
    const int b  = blockIdx.z;

    const int nfq = g_cnt[b * 2] + 1;
    if (n0 >= nfq) return;

    ull acc[4][4];
    #pragma unroll
    for (int mp = 0; mp < 4; mp++)
        #pragma unroll
        for (int jj = 0; jj < 4; jj++) acc[mp][jj] = 0ull;

    for (int kc = 0; kc < NC; kc += 32) {
        #pragma unroll
        for (int it = 0; it < 16; it++) {
            int idx = tid + it * 256;
            int m = idx >> 5, kk = idx & 31;
            Ws[kk][m] = Wo[(m0 + m) * 256 + kc + kk];
        }
        #pragma unroll
        for (int it = 0; it < 2; it++) {
            int idx = tid + it * 256;
            int k = idx >> 4, j4 = idx & 15;
            *reinterpret_cast<float4*>(&Xs[k][j4 * 4]) =
                *reinterpret_cast<const float4*>(&g_go[(size_t)(b * NC + kc + k) * NPQ + n0 + j4 * 4]);
        }
        __syncthreads();
        #pragma unroll 8
        for (int k = 0; k < 32; k++) {
            ulonglong2 w01 = *reinterpret_cast<const ulonglong2*>(&Ws[k][ty * 8]);
            ulonglong2 w23 = *reinterpret_cast<const ulonglong2*>(&Ws[k][ty * 8 + 4]);
            float4 xv = *reinterpret_cast<const float4*>(&Xs[k][tx * 4]);
            ull wp[4] = { w01.x, w01.y, w23.x, w23.y };
            ull xd[4] = { pack2(xv.x, xv.x), pack2(xv.y, xv.y),
                          pack2(xv.z, xv.z), pack2(xv.w, xv.w) };
            #pragma unroll
            for (int mp = 0; mp < 4; mp++)
                #pragma unroll
                for (int jj = 0; jj < 4; jj++)
                    acc[mp][jj] = fma2(wp[mp], xd[jj], acc[mp][jj]);
        }
        __syncthreads();
    }

    #pragma unroll
    for (int mp = 0; mp < 4; mp++) {
        float2 u[4];
        #pragma unroll
        for (int jj = 0; jj < 4; jj++) u[jj] = unpack2(acc[mp][jj]);
        #pragma unroll
        for (int h = 0; h < 2; h++) {
            int o = m0 + ty * 8 + mp * 2 + h;
            float bb = bo[o];
            float4 r;
            r.x = (h ? u[0].y : u[0].x) + bb;
            r.y = (h ? u[1].y : u[1].x) + bb;
            r.z = (h ? u[2].y : u[2].x) + bb;
            r.w = (h ? u[3].y : u[3].x) + bb;
            *reinterpret_cast<float4*>(&g_p[(size_t)(b * NC + o) * NPQ + n0 + tx * 4]) = r;
        }
    }
}

// ============================ scatter ======================================
__global__ __launch_bounds__(256, 1) void scatter_kernel(
    const float* __restrict__ x, const float* __restrict__ gamma,
    float* __restrict__ out)
{
    const int b = blockIdx.y;
    const int n = blockIdx.x * 256 + threadIdx.x;
    const int ci = g_cidx[(size_t)b * NP + n];
    const float g0 = gamma[0];

    const float* px = x + (size_t)b * NC * NP + n;
    const float* pp = g_p + (size_t)b * NC * NPQ + ci;
    float* po = out + (size_t)b * NC * NP + n;

    #pragma unroll 4
    for (int c = 0; c < NC; c++) {
        po[(size_t)c * NP] = pp[(size_t)c * NPQ] + g0 * px[(size_t)c * NP];
    }
}

extern "C" void kernel_launch(void* const* d_in, const int* in_sizes, int n_in,
                              void* d_out, int out_size)
{
    const float* x     = (const float*)d_in[0];
    const float* mask  = (const float*)d_in[1];
    const float* Wq    = (const float*)d_in[2];
    const float* bq    = (const float*)d_in[3];
    const float* Wk    = (const float*)d_in[4];
    const float* bk    = (const float*)d_in[5];
    const float* Wv    = (const float*)d_in[6];
    const float* bv    = (const float*)d_in[7];
    const float* Wo    = (const float*)d_in[8];
    const float* bo    = (const float*)d_in[9];
    const float* gamma = (const float*)d_in[10];
    float* out = (float*)d_out;

    compact_kernel<<<NB, 256>>>(mask);
    qkv_kernel<<<dim3(64, 6, NB), 256>>>(x, mask, Wq, bq, Wk, bk, Wv, bv);
    pad_kernel<<<dim3(NB, 3), 256>>>(bq, bk, bv);

    const size_t smemB = (size_t)(16384 + 32768 + 8192 + 256) * sizeof(float);  // 230400 B
    cudaFuncSetAttribute(attn_kernel, cudaFuncAttributeMaxDynamicSharedMemorySize, (int)smemB);
    attn_kernel<<<dim3(65, NB), 512, smemB>>>();

    proj_kernel<<<dim3(65, 2, NB), 256>>>(Wo, bo);
    scatter_kernel<<<dim3(16, NB), 256>>>(x, gamma, out);
}